// round 11
// baseline (speedup 1.0000x reference)
#include <cuda_runtime.h>
#include <cuda_fp16.h>
#include <cstdint>

// NCC loss, 9x9 box, SAME zero pad, n=81 (matches reference conv).
// Round 11: 7 blocks/SM (28 warps).
//   - staging descriptors packed into one u32/vec (meta): frees ~10 regs.
//   - __launch_bounds__(128, 7): 72-reg cap.
//   - everything else = Round-10 winner (62.2us): fp16-compressed ring,
//     fp32 S + exact-cancellation slide, 3-row stages, depth-4 cp.async,
//     wait_group 2, uniform commit, 1 barrier/stage, merged epilogue,
//     deterministic fused reduction.

#define WW 512
#define HH 512
#define NB 32
#define COLS 128
#define STRIPH 64
#define NBLK (4 * 8 * 32)   // 1024 blocks
#define NSTAGE 24           // 72 row-steps / 3 rows per stage
#define VECS_PER_STAGE 306  // 9 row-images * 34 float4

__device__ float        g_partials[NBLK];
__device__ unsigned int g_count = 0;

__device__ __forceinline__ void cp16(uint32_t dst, const float* src, bool ok) {
    asm volatile("cp.async.cg.shared.global [%0], [%1], 16, %2;"
                 :: "r"(dst), "l"(src), "r"(ok ? 16 : 0) : "memory");
}
__device__ __forceinline__ void cp_commit() {
    asm volatile("cp.async.commit_group;" ::: "memory");
}
__device__ __forceinline__ void cp_wait2() {
    asm volatile("cp.async.wait_group 2;" ::: "memory");
}

__global__ __launch_bounds__(128, 7)
void ncc_fused(const float* __restrict__ img1,
               const float* __restrict__ img2,
               const float* __restrict__ fus,
               float* __restrict__ out)
{
    const int tid   = threadIdx.x;
    const int xbase = blockIdx.x * COLS;
    const int ybase = blockIdx.y * STRIPH;
    const int b     = blockIdx.z;

    const size_t base = (size_t)b * (size_t)(HH * WW);
    const float* p1 = img1 + base;
    const float* p2 = img2 + base;
    const float* pf = fus  + base;

    // 4 buffers x (3 imgs x 3 rows) x 136 floats (544B rows, 16B aligned)
    __shared__ float rows[4][9][136];
    __shared__ float red[4];
    __shared__ int   lastflag;

    const uint32_t smem_rows = (uint32_t)__cvta_generic_to_shared(&rows[0][0][0]);

    // ---- packed staging descriptors: 1 u32 + 1 pointer per vec ----
    // meta = doff(bits 0..19) | joff(bits 20..21) | cok(bit 24) | act(bit 25)
    const float* pb[3];
    uint32_t     meta[3];
#pragma unroll
    for (int it = 0; it < 3; ++it) {
        const int i   = tid + 128 * it;
        const bool ac = (i < VECS_PER_STAGE);
        const int ii  = ac ? i : 0;
        const int ri  = ii / 34;            // row-image 0..8 = img*3 + jj
        const int vec = ii - ri * 34;
        const int img = ri / 3;
        const int jj  = ri - img * 3;
        const int gx  = xbase - 4 + vec * 4;
        const bool ck = (gx >= 0) && (gx <= WW - 4);
        const float* p = (img == 0) ? p1 : ((img == 1) ? p2 : pf);
        pb[it]   = p + (ck ? gx : 0);
        meta[it] = (uint32_t)((ri * 136 + vec * 4) * 4)
                 | ((uint32_t)jj << 20)
                 | (ck ? (1u << 24) : 0u)
                 | (ac ? (1u << 25) : 0u);
    }

    auto stage = [&](int s, int buf) {
        const int r0 = ybase - 4 + 3 * s;
        const uint32_t bb = smem_rows + (uint32_t)(buf * (9 * 136 * 4));
#pragma unroll
        for (int it = 0; it < 3; ++it) {
            const uint32_t m = meta[it];
            if (m & (1u << 25)) {
                const int  r   = r0 + (int)((m >> 20) & 3u);
                const bool rok = ((unsigned)r < (unsigned)HH);
                const int  rc  = rok ? r : 0;
                const bool ok  = rok && (m & (1u << 24));
                cp16(bb + (m & 0xFFFFFu), pb[it] + (size_t)rc * WW, ok);
            }
        }
    };

    // fp16-compressed 9-deep ring: 4 half2 regs per slot = 36 regs total
    __half2 ring[9][4];
    float S[8];
#pragma unroll
    for (int j = 0; j < 9; ++j)
#pragma unroll
        for (int q = 0; q < 4; ++q) ring[j][q] = __floats2half2_rn(0.0f, 0.0f);
#pragma unroll
    for (int q = 0; q < 8; ++q) S[q] = 0.0f;

    float acc = 0.0f;
    const float inv_n = 1.0f / 81.0f;

    stage(0, 0); cp_commit();
    stage(1, 1); cp_commit();
    stage(2, 2); cp_commit();

    for (int a = 0; a < 8; ++a) {
#pragma unroll
        for (int g = 0; g < 3; ++g) {
            const int s   = 3 * a + g;
            const int buf = s & 3;
            // pending groups: s, s+1, s+2 (later ones may be empty commits)
            cp_wait2();
            __syncthreads();

            if (s + 3 < NSTAGE) stage(s + 3, (s + 3) & 3);
            cp_commit();       // unconditional: uniform group accounting

            const float (*R)[136] = rows[buf];

#pragma unroll
            for (int j = 0; j < 3; ++j) {
                const int slot = 3 * g + j;     // static 0..8 == (9a+slot) % 9

                // ---- horizontal 9-tap sums of the 8 fields (fp32) ----
                float h0 = 0.f, h1 = 0.f, h2 = 0.f, h3 = 0.f;
                float h4 = 0.f, h5 = 0.f, h6 = 0.f, h7 = 0.f;
#pragma unroll
                for (int k = 0; k < 9; ++k) {
                    const float av = R[0 + j][tid + k];
                    const float cv = R[3 + j][tid + k];
                    const float fv = R[6 + j][tid + k];
                    h0 += av;
                    h1 = fmaf(av, av, h1);
                    h2 = fmaf(av, fv, h2);
                    h3 += cv;
                    h4 = fmaf(cv, cv, h4);
                    h5 = fmaf(cv, fv, h5);
                    h6 += fv;
                    h7 = fmaf(fv, fv, h7);
                }

                // ---- quantize to fp16 pairs (same value enters AND exits) ----
                const __half2 q0 = __floats2half2_rn(h0, h1);
                const __half2 q1 = __floats2half2_rn(h2, h3);
                const __half2 q2 = __floats2half2_rn(h4, h5);
                const __half2 q3 = __floats2half2_rn(h6, h7);

                const float2 n0 = __half22float2(q0);
                const float2 n1 = __half22float2(q1);
                const float2 n2 = __half22float2(q2);
                const float2 n3 = __half22float2(q3);
                const float2 o0 = __half22float2(ring[slot][0]);
                const float2 o1 = __half22float2(ring[slot][1]);
                const float2 o2 = __half22float2(ring[slot][2]);
                const float2 o3 = __half22float2(ring[slot][3]);

                // ---- vertical slide in fp32 (exact cancellation) ----
                S[0] += n0.x - o0.x;  S[1] += n0.y - o0.y;
                S[2] += n1.x - o1.x;  S[3] += n1.y - o1.y;
                S[4] += n2.x - o2.x;  S[5] += n2.y - o2.y;
                S[6] += n3.x - o3.x;  S[7] += n3.y - o3.y;

                ring[slot][0] = q0;
                ring[slot][1] = q1;
                ring[slot][2] = q2;
                ring[slot][3] = q3;

                // ---- emit output row (row-step i = 9a+slot >= 8) ----
                if (a > 0 || slot >= 8) {
                    const float mA = S[0] * inv_n;
                    const float mB = S[3] * inv_n;
                    const float mJ = S[6] * inv_n;
                    const float crossA = fmaf(-mA, S[6], S[2]);
                    const float varA   = fmaf(-mA, S[0], S[1]);
                    const float varJ   = fmaf(-mJ, S[6], S[7]);
                    const float crossB = fmaf(-mB, S[6], S[5]);
                    const float varB   = fmaf(-mB, S[3], S[4]);
                    const float dA = fmaf(varA, varJ, 1e-5f);
                    const float dB = fmaf(varB, varJ, 1e-5f);
                    // ccA + ccB = (crossA^2*dB + crossB^2*dA) / (dA*dB)
                    const float num = fmaf(crossB * crossB, dA,
                                           crossA * crossA * dB);
                    const float rcp = __fdividef(1.0f, dA * dB);
                    acc = fmaf(-num, rcp, acc + 2.0f);   // += 2 - (ccA+ccB)
                }
            }
            // no bottom barrier: next iteration's top __syncthreads protects
            // buffer reuse (depth-4 ring, refill target last read 3 stages ago)
        }
    }

    // ---- deterministic block reduction ----
#pragma unroll
    for (int off = 16; off > 0; off >>= 1)
        acc += __shfl_xor_sync(0xffffffffu, acc, off);
    if ((tid & 31) == 0) red[tid >> 5] = acc;
    __syncthreads();

    const int bidx = (blockIdx.z * 8 + blockIdx.y) * 4 + blockIdx.x;
    if (tid == 0) {
        g_partials[bidx] = (red[0] + red[1]) + (red[2] + red[3]);
        __threadfence();
        unsigned int old = atomicInc(&g_count, NBLK - 1);  // wraps: graph-replay safe
        lastflag = (old == NBLK - 1);
    }
    __syncthreads();

    if (lastflag) {
        float v = 0.0f;
#pragma unroll
        for (int m = 0; m < NBLK / 128; ++m)
            v += g_partials[tid + 128 * m];
#pragma unroll
        for (int off = 16; off > 0; off >>= 1)
            v += __shfl_xor_sync(0xffffffffu, v, off);
        if ((tid & 31) == 0) red[tid >> 5] = v;
        __syncthreads();
        if (tid == 0) {
            const float tot = (red[0] + red[1]) + (red[2] + red[3]);
            // mean(combined) = sum(2*combined) * 0.5 / 2^23 = tot * 2^-24
            out[0] = tot * 5.9604644775390625e-08f;
        }
    }
}

extern "C" void kernel_launch(void* const* d_in, const int* in_sizes, int n_in,
                              void* d_out, int out_size)
{
    (void)in_sizes; (void)n_in; (void)out_size;
    const float* img1 = (const float*)d_in[0];
    const float* img2 = (const float*)d_in[1];
    const float* fus  = (const float*)d_in[2];

    dim3 grid(4, 8, NB);   // 1024 blocks
    ncc_fused<<<grid, 128>>>(img1, img2, fus, (float*)d_out);
}

// round 12
// speedup vs baseline: 1.0885x; 1.0885x over previous
#include <cuda_runtime.h>
#include <cuda_fp16.h>
#include <cstdint>

// NCC loss, 9x9 box, SAME zero pad, n=81 (matches reference conv).
// Round 12: R10 champion chassis (62.2us) + two surgical cuts:
//   (1) slide uses raw fp32 h on entry (no dequant of the new value):
//       S += h - dequant(ring_old). Quantization residual accumulates in S
//       (<=4e-4 relative, random sign) -> loss error ~3e-6, tol 1e-3.
//       Saves 8 cvt insts/px.
//   (2) depth-6 cp.async pipeline, wait_group 4 (prefetch distance 5 stages),
//       same 3-row stage granularity. smem 29.4KB x 6 blocks fits.
// Unchanged: fp16-compressed ring, fp32 S, __launch_bounds__(128,6) (80-reg
// sweet spot), 1 barrier/stage, hoisted staging descriptors, merged epilogue,
// deterministic fused reduction.

#define WW 512
#define HH 512
#define NB 32
#define COLS 128
#define STRIPH 64
#define NBLK (4 * 8 * 32)   // 1024 blocks
#define NSTAGE 24           // 72 row-steps / 3 rows per stage
#define VECS_PER_STAGE 306  // 9 row-images * 34 float4

__device__ float        g_partials[NBLK];
__device__ unsigned int g_count = 0;

__device__ __forceinline__ void cp16(uint32_t dst, const float* src, bool ok) {
    asm volatile("cp.async.cg.shared.global [%0], [%1], 16, %2;"
                 :: "r"(dst), "l"(src), "r"(ok ? 16 : 0) : "memory");
}
__device__ __forceinline__ void cp_commit() {
    asm volatile("cp.async.commit_group;" ::: "memory");
}
__device__ __forceinline__ void cp_wait4() {
    asm volatile("cp.async.wait_group 4;" ::: "memory");
}

__global__ __launch_bounds__(128, 6)
void ncc_fused(const float* __restrict__ img1,
               const float* __restrict__ img2,
               const float* __restrict__ fus,
               float* __restrict__ out)
{
    const int tid   = threadIdx.x;
    const int xbase = blockIdx.x * COLS;
    const int ybase = blockIdx.y * STRIPH;
    const int b     = blockIdx.z;

    const size_t base = (size_t)b * (size_t)(HH * WW);
    const float* p1 = img1 + base;
    const float* p2 = img2 + base;
    const float* pf = fus  + base;

    // 6 buffers x (3 imgs x 3 rows) x 136 floats (544B rows, 16B aligned)
    __shared__ float rows[6][9][136];
    __shared__ float red[4];
    __shared__ int   lastflag;

    const uint32_t smem_rows = (uint32_t)__cvta_generic_to_shared(&rows[0][0][0]);

    // ---- loop-invariant staging descriptors (3 vecs per thread) ----
    const float* pb[3];      // image pointer pre-offset by (safe) column
    int          joff[3];    // row-within-stage 0..2
    uint32_t     doff[3];    // dst byte offset within a buffer
    bool         cokv[3];    // column-window valid
    bool         act[3];     // vec index < 306
#pragma unroll
    for (int it = 0; it < 3; ++it) {
        const int i  = tid + 128 * it;
        act[it]      = (i < VECS_PER_STAGE);
        const int ii  = act[it] ? i : 0;
        const int ri  = ii / 34;            // row-image 0..8 = img*3 + jj
        const int vec = ii - ri * 34;
        const int img = ri / 3;
        joff[it]      = ri - img * 3;
        const int gx  = xbase - 4 + vec * 4;
        const bool ck = (gx >= 0) && (gx <= WW - 4);
        cokv[it]      = ck;
        const float* p = (img == 0) ? p1 : ((img == 1) ? p2 : pf);
        pb[it]        = p + (ck ? gx : 0);
        doff[it]      = (uint32_t)((ri * 136 + vec * 4) * 4);
    }

    auto stage = [&](int s, int buf) {
        const int r0 = ybase - 4 + 3 * s;
        const uint32_t bb = smem_rows + (uint32_t)(buf * (9 * 136 * 4));
#pragma unroll
        for (int it = 0; it < 3; ++it) {
            if (act[it]) {
                const int  r   = r0 + joff[it];
                const bool rok = ((unsigned)r < (unsigned)HH);
                const int  rc  = rok ? r : 0;
                cp16(bb + doff[it], pb[it] + (size_t)rc * WW, rok && cokv[it]);
            }
        }
    };

    // fp16-compressed 9-deep ring: 4 half2 regs per slot = 36 regs total
    __half2 ring[9][4];
    float S[8];
#pragma unroll
    for (int j = 0; j < 9; ++j)
#pragma unroll
        for (int q = 0; q < 4; ++q) ring[j][q] = __floats2half2_rn(0.0f, 0.0f);
#pragma unroll
    for (int q = 0; q < 8; ++q) S[q] = 0.0f;

    float acc = 0.0f;
    const float inv_n = 1.0f / 81.0f;

    stage(0, 0); cp_commit();
    stage(1, 1); cp_commit();
    stage(2, 2); cp_commit();
    stage(3, 3); cp_commit();
    stage(4, 4); cp_commit();

    for (int a = 0; a < 8; ++a) {
        const int p = (a & 1) * 3;          // buf(s=3a+g) = p + g
        const int q = 3 - p;
#pragma unroll
        for (int g = 0; g < 3; ++g) {
            const int s   = 3 * a + g;
            const int buf = p + g;          // == s % 6
            // pending groups: s .. s+4 (later ones may be empty commits)
            cp_wait4();
            __syncthreads();

            // refill target = (s+5) % 6 == (s-1) % 6 (read in the previous iter)
            const int rbuf = (g == 0) ? (q + 2) : (p + g - 1);
            if (s + 5 < NSTAGE) stage(s + 5, rbuf);
            cp_commit();       // unconditional: uniform group accounting

            const float (*R)[136] = rows[buf];

#pragma unroll
            for (int j = 0; j < 3; ++j) {
                const int slot = 3 * g + j;     // static 0..8 == (9a+slot) % 9

                // ---- horizontal 9-tap sums of the 8 fields (fp32) ----
                float h0 = 0.f, h1 = 0.f, h2 = 0.f, h3 = 0.f;
                float h4 = 0.f, h5 = 0.f, h6 = 0.f, h7 = 0.f;
#pragma unroll
                for (int k = 0; k < 9; ++k) {
                    const float av = R[0 + j][tid + k];
                    const float cv = R[3 + j][tid + k];
                    const float fv = R[6 + j][tid + k];
                    h0 += av;
                    h1 = fmaf(av, av, h1);
                    h2 = fmaf(av, fv, h2);
                    h3 += cv;
                    h4 = fmaf(cv, cv, h4);
                    h5 = fmaf(cv, fv, h5);
                    h6 += fv;
                    h7 = fmaf(fv, fv, h7);
                }

                // ---- dequantize only the RETIRING entry ----
                const float2 o0 = __half22float2(ring[slot][0]);
                const float2 o1 = __half22float2(ring[slot][1]);
                const float2 o2 = __half22float2(ring[slot][2]);
                const float2 o3 = __half22float2(ring[slot][3]);

                // ---- vertical slide: raw h in, quantized value out ----
                S[0] += h0 - o0.x;  S[1] += h1 - o0.y;
                S[2] += h2 - o1.x;  S[3] += h3 - o1.y;
                S[4] += h4 - o2.x;  S[5] += h5 - o2.y;
                S[6] += h6 - o3.x;  S[7] += h7 - o3.y;

                ring[slot][0] = __floats2half2_rn(h0, h1);
                ring[slot][1] = __floats2half2_rn(h2, h3);
                ring[slot][2] = __floats2half2_rn(h4, h5);
                ring[slot][3] = __floats2half2_rn(h6, h7);

                // ---- emit output row (row-step i = 9a+slot >= 8) ----
                if (a > 0 || slot >= 8) {
                    const float mA = S[0] * inv_n;
                    const float mB = S[3] * inv_n;
                    const float mJ = S[6] * inv_n;
                    const float crossA = fmaf(-mA, S[6], S[2]);
                    const float varA   = fmaf(-mA, S[0], S[1]);
                    const float varJ   = fmaf(-mJ, S[6], S[7]);
                    const float crossB = fmaf(-mB, S[6], S[5]);
                    const float varB   = fmaf(-mB, S[3], S[4]);
                    const float dA = fmaf(varA, varJ, 1e-5f);
                    const float dB = fmaf(varB, varJ, 1e-5f);
                    // ccA + ccB = (crossA^2*dB + crossB^2*dA) / (dA*dB)
                    const float num = fmaf(crossB * crossB, dA,
                                           crossA * crossA * dB);
                    const float rcp = __fdividef(1.0f, dA * dB);
                    acc = fmaf(-num, rcp, acc + 2.0f);   // += 2 - (ccA+ccB)
                }
            }
            // no bottom barrier: next iteration's top __syncthreads protects
            // buffer reuse (depth-6 ring, refill target last read 1 iter ago)
        }
    }

    // ---- deterministic block reduction ----
#pragma unroll
    for (int off = 16; off > 0; off >>= 1)
        acc += __shfl_xor_sync(0xffffffffu, acc, off);
    if ((tid & 31) == 0) red[tid >> 5] = acc;
    __syncthreads();

    const int bidx = (blockIdx.z * 8 + blockIdx.y) * 4 + blockIdx.x;
    if (tid == 0) {
        g_partials[bidx] = (red[0] + red[1]) + (red[2] + red[3]);
        __threadfence();
        unsigned int old = atomicInc(&g_count, NBLK - 1);  // wraps: graph-replay safe
        lastflag = (old == NBLK - 1);
    }
    __syncthreads();

    if (lastflag) {
        float v = 0.0f;
#pragma unroll
        for (int m = 0; m < NBLK / 128; ++m)
            v += g_partials[tid + 128 * m];
#pragma unroll
        for (int off = 16; off > 0; off >>= 1)
            v += __shfl_xor_sync(0xffffffffu, v, off);
        if ((tid & 31) == 0) red[tid >> 5] = v;
        __syncthreads();
        if (tid == 0) {
            const float tot = (red[0] + red[1]) + (red[2] + red[3]);
            // mean(combined) = sum(2*combined) * 0.5 / 2^23 = tot * 2^-24
            out[0] = tot * 5.9604644775390625e-08f;
        }
    }
}

extern "C" void kernel_launch(void* const* d_in, const int* in_sizes, int n_in,
                              void* d_out, int out_size)
{
    (void)in_sizes; (void)n_in; (void)out_size;
    const float* img1 = (const float*)d_in[0];
    const float* img2 = (const float*)d_in[1];
    const float* fus  = (const float*)d_in[2];

    dim3 grid(4, 8, NB);   // 1024 blocks
    ncc_fused<<<grid, 128>>>(img1, img2, fus, (float*)d_out);
}

// round 13
// speedup vs baseline: 1.2595x; 1.1571x over previous
#include <cuda_runtime.h>
#include <cuda_fp16.h>
#include <cstdint>

// NCC loss, 9x9 box, SAME zero pad, n=81 (matches reference conv).
// Round 13: packed HFMA2 horizontal taps on the R10 champion chassis.
//   - per stage, staged fp32 rows are converted once into packed half2 pairs
//     W[x] = {P=(a,c), G=(f,1)} (flat index u=r*136+x matches staged layout).
//   - each tap: 1 LDS.64 + 1 PRMT (Q=(f,f)) + 4 packed ops:
//       A1+=P            -> (Sa,  Sc)
//       A2=hfma2(P,P,A2) -> (Saa, Scc)
//       A3=hfma2(P,Q,A3) -> (Saf, Scf)
//       A4=hfma2(G,Q,A4) -> (Sff, Sf)
//     54 insts/px vs 99 for the scalar version.
//   - ring stores A1..A4 directly (no separate quantization); dequant is
//     identical on entry and exit -> exact sliding-window cancellation; S fp32.
//   - chassis: depth-4 cp.async, wait_group 2, uniform commit, 2 barriers/stage
//     (conversion needs one extra), __launch_bounds__(128,6), grid 4x8x32.
// Deterministic fused reduction (fixed-order, wrapping atomicInc).

#define WW 512
#define HH 512
#define NB 32
#define COLS 128
#define STRIPH 64
#define NBLK (4 * 8 * 32)   // 1024 blocks
#define NSTAGE 24           // 72 row-steps / 3 rows per stage
#define VECS_PER_STAGE 306  // 9 row-images * 34 float4
#define UNITS 408           // 3 rows * 136 cols per stage (conversion units)

__device__ float        g_partials[NBLK];
__device__ unsigned int g_count = 0;

__device__ __forceinline__ void cp16(uint32_t dst, const float* src, bool ok) {
    asm volatile("cp.async.cg.shared.global [%0], [%1], 16, %2;"
                 :: "r"(dst), "l"(src), "r"(ok ? 16 : 0) : "memory");
}
__device__ __forceinline__ void cp_commit() {
    asm volatile("cp.async.commit_group;" ::: "memory");
}
__device__ __forceinline__ void cp_wait2() {
    asm volatile("cp.async.wait_group 2;" ::: "memory");
}

__global__ __launch_bounds__(128, 6)
void ncc_fused(const float* __restrict__ img1,
               const float* __restrict__ img2,
               const float* __restrict__ fus,
               float* __restrict__ out)
{
    const int tid   = threadIdx.x;
    const int xbase = blockIdx.x * COLS;
    const int ybase = blockIdx.y * STRIPH;
    const int b     = blockIdx.z;

    const size_t base = (size_t)b * (size_t)(HH * WW);
    const float* p1 = img1 + base;
    const float* p2 = img2 + base;
    const float* pf = fus  + base;

    // 4 buffers x (3 imgs x 3 rows) x 136 floats; image-major: a rows 0-2,
    // c rows 3-5, f rows 6-8  ->  flat float index: img*408 + r*136 + x
    __shared__ float rows[4][9][136];
    // packed taps for the CURRENT stage: uint2 {P=(a,c), G=(f,1)} per (r,x)
    __shared__ __align__(16) uint2 W[UNITS];
    __shared__ float red[4];
    __shared__ int   lastflag;

    const uint32_t smem_rows = (uint32_t)__cvta_generic_to_shared(&rows[0][0][0]);

    // ---- loop-invariant staging descriptors (3 vecs per thread) ----
    const float* pb[3];
    int          joff[3];
    uint32_t     doff[3];
    bool         cokv[3];
    bool         act[3];
#pragma unroll
    for (int it = 0; it < 3; ++it) {
        const int i  = tid + 128 * it;
        act[it]      = (i < VECS_PER_STAGE);
        const int ii  = act[it] ? i : 0;
        const int ri  = ii / 34;            // row-image 0..8 = img*3 + jj
        const int vec = ii - ri * 34;
        const int img = ri / 3;
        joff[it]      = ri - img * 3;
        const int gx  = xbase - 4 + vec * 4;
        const bool ck = (gx >= 0) && (gx <= WW - 4);
        cokv[it]      = ck;
        const float* p = (img == 0) ? p1 : ((img == 1) ? p2 : pf);
        pb[it]        = p + (ck ? gx : 0);
        doff[it]      = (uint32_t)((ri * 136 + vec * 4) * 4);
    }

    auto stage = [&](int s, int buf) {
        const int r0 = ybase - 4 + 3 * s;
        const uint32_t bb = smem_rows + (uint32_t)(buf * (9 * 136 * 4));
#pragma unroll
        for (int it = 0; it < 3; ++it) {
            if (act[it]) {
                const int  r   = r0 + joff[it];
                const bool rok = ((unsigned)r < (unsigned)HH);
                const int  rc  = rok ? r : 0;
                cp16(bb + doff[it], pb[it] + (size_t)rc * WW, rok && cokv[it]);
            }
        }
    };

    // ring stores the packed tap results A1..A4 (4 half2 per slot = 36 regs)
    __half2 ring[9][4];
    float S[8];
#pragma unroll
    for (int j = 0; j < 9; ++j)
#pragma unroll
        for (int q = 0; q < 4; ++q) ring[j][q] = __floats2half2_rn(0.0f, 0.0f);
#pragma unroll
    for (int q = 0; q < 8; ++q) S[q] = 0.0f;

    float acc = 0.0f;
    const float inv_n = 1.0f / 81.0f;

    stage(0, 0); cp_commit();
    stage(1, 1); cp_commit();
    stage(2, 2); cp_commit();

    for (int a = 0; a < 8; ++a) {
#pragma unroll
        for (int g = 0; g < 3; ++g) {
            const int s   = 3 * a + g;
            const int buf = s & 3;
            // pending groups: s, s+1, s+2 (later ones may be empty commits)
            cp_wait2();
            __syncthreads();   // staged fp32 visible to all; prev W reads done

            // ---- conversion pass: staged fp32 -> packed W (flat index) ----
            {
                const float* Rf32 = &rows[buf][0][0];
#pragma unroll
                for (int it = 0; it < 4; ++it) {
                    const int u = tid + 128 * it;
                    if (u < UNITS) {
                        const float av = Rf32[u];
                        const float cv = Rf32[u + 408];
                        const float fv = Rf32[u + 816];
                        const __half2 P = __floats2half2_rn(av, cv);
                        const __half2 G = __floats2half2_rn(fv, 1.0f);
                        uint2 pk;
                        pk.x = *reinterpret_cast<const unsigned*>(&P);
                        pk.y = *reinterpret_cast<const unsigned*>(&G);
                        W[u] = pk;
                    }
                }
            }
            __syncthreads();   // W visible to all

            if (s + 3 < NSTAGE) stage(s + 3, (s + 3) & 3);
            cp_commit();       // unconditional: uniform group accounting

#pragma unroll
            for (int j = 0; j < 3; ++j) {
                const int slot = 3 * g + j;     // static 0..8 == (9a+slot) % 9

                // ---- packed 9-tap horizontal sums ----
                __half2 A1 = __floats2half2_rn(0.0f, 0.0f);
                __half2 A2 = A1, A3 = A1, A4 = A1;
#pragma unroll
                for (int k = 0; k < 9; ++k) {
                    const uint2 pk = W[j * 136 + tid + k];
                    const __half2 P = *reinterpret_cast<const __half2*>(&pk.x);
                    const __half2 G = *reinterpret_cast<const __half2*>(&pk.y);
                    const __half2 Q = __low2half2(G);   // (f,f)
                    A1 = __hadd2(A1, P);                // (Sa,  Sc)
                    A2 = __hfma2(P, P, A2);             // (Saa, Scc)
                    A3 = __hfma2(P, Q, A3);             // (Saf, Scf)
                    A4 = __hfma2(G, Q, A4);             // (Sff, Sf)
                }

                // ---- dequantize new and retiring entries (identical path) ----
                const float2 u1 = __half22float2(A1);
                const float2 u2 = __half22float2(A2);
                const float2 u3 = __half22float2(A3);
                const float2 u4 = __half22float2(A4);
                const float2 o1 = __half22float2(ring[slot][0]);
                const float2 o2 = __half22float2(ring[slot][1]);
                const float2 o3 = __half22float2(ring[slot][2]);
                const float2 o4 = __half22float2(ring[slot][3]);

                // ---- vertical slide in fp32 (exact cancellation) ----
                S[0] += u1.x - o1.x;  S[3] += u1.y - o1.y;
                S[1] += u2.x - o2.x;  S[4] += u2.y - o2.y;
                S[2] += u3.x - o3.x;  S[5] += u3.y - o3.y;
                S[7] += u4.x - o4.x;  S[6] += u4.y - o4.y;

                ring[slot][0] = A1;
                ring[slot][1] = A2;
                ring[slot][2] = A3;
                ring[slot][3] = A4;

                // ---- emit output row (row-step i = 9a+slot >= 8) ----
                if (a > 0 || slot >= 8) {
                    const float mA = S[0] * inv_n;
                    const float mB = S[3] * inv_n;
                    const float mJ = S[6] * inv_n;
                    const float crossA = fmaf(-mA, S[6], S[2]);
                    const float varA   = fmaf(-mA, S[0], S[1]);
                    const float varJ   = fmaf(-mJ, S[6], S[7]);
                    const float crossB = fmaf(-mB, S[6], S[5]);
                    const float varB   = fmaf(-mB, S[3], S[4]);
                    const float dA = fmaf(varA, varJ, 1e-5f);
                    const float dB = fmaf(varB, varJ, 1e-5f);
                    // ccA + ccB = (crossA^2*dB + crossB^2*dA) / (dA*dB)
                    const float num = fmaf(crossB * crossB, dA,
                                           crossA * crossA * dB);
                    const float rcp = __fdividef(1.0f, dA * dB);
                    acc = fmaf(-num, rcp, acc + 2.0f);   // += 2 - (ccA+ccB)
                }
            }
            // no bottom barrier: next iteration's first __syncthreads protects
            // both the fp32 buffer ring (depth 4) and the W buffer
        }
    }

    // ---- deterministic block reduction ----
#pragma unroll
    for (int off = 16; off > 0; off >>= 1)
        acc += __shfl_xor_sync(0xffffffffu, acc, off);
    if ((tid & 31) == 0) red[tid >> 5] = acc;
    __syncthreads();

    const int bidx = (blockIdx.z * 8 + blockIdx.y) * 4 + blockIdx.x;
    if (tid == 0) {
        g_partials[bidx] = (red[0] + red[1]) + (red[2] + red[3]);
        __threadfence();
        unsigned int old = atomicInc(&g_count, NBLK - 1);  // wraps: graph-replay safe
        lastflag = (old == NBLK - 1);
    }
    __syncthreads();

    if (lastflag) {
        float v = 0.0f;
#pragma unroll
        for (int m = 0; m < NBLK / 128; ++m)
            v += g_partials[tid + 128 * m];
#pragma unroll
        for (int off = 16; off > 0; off >>= 1)
            v += __shfl_xor_sync(0xffffffffu, v, off);
        if ((tid & 31) == 0) red[tid >> 5] = v;
        __syncthreads();
        if (tid == 0) {
            const float tot = (red[0] + red[1]) + (red[2] + red[3]);
            // mean(combined) = sum(2*combined) * 0.5 / 2^23 = tot * 2^-24
            out[0] = tot * 5.9604644775390625e-08f;
        }
    }
}

extern "C" void kernel_launch(void* const* d_in, const int* in_sizes, int n_in,
                              void* d_out, int out_size)
{
    (void)in_sizes; (void)n_in; (void)out_size;
    const float* img1 = (const float*)d_in[0];
    const float* img2 = (const float*)d_in[1];
    const float* fus  = (const float*)d_in[2];

    dim3 grid(4, 8, NB);   // 1024 blocks
    ncc_fused<<<grid, 128>>>(img1, img2, fus, (float*)d_out);
}